// round 6
// baseline (speedup 1.0000x reference)
#include <cuda_runtime.h>
#include <math.h>

// R5 = R4 resubmission (R4 bench was an infra failure, theory untested).
// Theory: replicate reference op order exactly — single serial-k concat GEMM
// with post-sum bias, reference-ordered log-softmax, de-fused elementwise.

// Problem constants
#define B     2048
#define L     256
#define H     1024
#define D     256
#define NSTEP 64
#define G3H   (3*H)   // 3072
#define KIN   (D + L) // 512, concat input width

// ---------------- scratch (device globals: allocation-free) ----------------
__device__ float g_inp [(size_t)B * KIN];   // [out_t | z] concat buffer
__device__ float g_gi  [(size_t)B * G3H];
__device__ float g_gh  [(size_t)B * G3H];
__device__ float g_h1  [(size_t)B * H];
__device__ float g_h2  [(size_t)B * H];
__device__ float g_tmp [(size_t)B * D];     // pre-softmax logits

// ---------------- tiled GEMM: C = act(A @ W^T + bias) ----------------------
// fp32, per-(m,n) accumulation is a SERIAL ascending-k FMA chain — matching
// cublas SIMT SGEMM semantics. Bias added AFTER the full K sum (XLA order).
// A: [M, lda] row-major, W: [N, ldw] row-major (product = A @ W^T).
#define BM 128
#define BN 64
#define BK 16

template<int ACT>
__global__ void __launch_bounds__(256, 4) gemm_kernel(
    const float* __restrict__ A, int lda,
    const float* __restrict__ W, int ldw,
    const float* __restrict__ bias,
    float* __restrict__ C,
    int N, int K)
{
    __shared__ float As[BK][BM + 4];
    __shared__ float Bs[BK][BN + 4];

    const int tid = threadIdx.x;
    const int tx  = tid & 15;     // 16 -> N direction
    const int ty  = tid >> 4;     // 16 -> M direction
    const int m0  = blockIdx.y * BM;
    const int n0  = blockIdx.x * BN;

    float acc[8][4];
    #pragma unroll
    for (int i = 0; i < 8; i++)
        #pragma unroll
        for (int j = 0; j < 4; j++) acc[i][j] = 0.f;

    for (int kt = 0; kt < K; kt += BK) {
        // Load A tile: 128x16 = 512 float4, 2 per thread
        #pragma unroll
        for (int l = 0; l < 2; l++) {
            int idx4 = tid + l * 256;
            int r = idx4 >> 2, c4 = idx4 & 3;
            float4 v = *reinterpret_cast<const float4*>(
                A + (size_t)(m0 + r) * lda + kt + c4 * 4);
            As[c4*4+0][r] = v.x; As[c4*4+1][r] = v.y;
            As[c4*4+2][r] = v.z; As[c4*4+3][r] = v.w;
        }
        // Load W tile: 64x16 = 256 float4, 1 per thread
        {
            int r = tid >> 2, c4 = tid & 3;
            float4 v = *reinterpret_cast<const float4*>(
                W + (size_t)(n0 + r) * ldw + kt + c4 * 4);
            Bs[c4*4+0][r] = v.x; Bs[c4*4+1][r] = v.y;
            Bs[c4*4+2][r] = v.z; Bs[c4*4+3][r] = v.w;
        }
        __syncthreads();

        // Serial ascending-k FMA chain per (m, n)
        #pragma unroll
        for (int k = 0; k < BK; k++) {
            float4 a0 = *reinterpret_cast<const float4*>(&As[k][ty * 8]);
            float4 a1 = *reinterpret_cast<const float4*>(&As[k][ty * 8 + 4]);
            float4 b0 = *reinterpret_cast<const float4*>(&Bs[k][tx * 4]);
            float av[8] = {a0.x, a0.y, a0.z, a0.w, a1.x, a1.y, a1.z, a1.w};
            float bv[4] = {b0.x, b0.y, b0.z, b0.w};
            #pragma unroll
            for (int i = 0; i < 8; i++)
                #pragma unroll
                for (int j = 0; j < 4; j++)
                    acc[i][j] = fmaf(av[i], bv[j], acc[i][j]);
        }
        __syncthreads();
    }

    // Epilogue: bias added AFTER the full sum (reference op order).
    float4 b4 = make_float4(0.f, 0.f, 0.f, 0.f);
    if (bias) b4 = *reinterpret_cast<const float4*>(bias + n0 + tx * 4);

    #pragma unroll
    for (int i = 0; i < 8; i++) {
        int m = m0 + ty * 8 + i;
        size_t off = (size_t)m * N + n0 + tx * 4;
        float4 v = make_float4(__fadd_rn(acc[i][0], b4.x),
                               __fadd_rn(acc[i][1], b4.y),
                               __fadd_rn(acc[i][2], b4.z),
                               __fadd_rn(acc[i][3], b4.w));
        if (ACT == 1) {
            v.x = tanhf(v.x); v.y = tanhf(v.y);
            v.z = tanhf(v.z); v.w = tanhf(v.w);
        }
        *reinterpret_cast<float4*>(C + off) = v;
    }
}

// ---------------- GRU gate fusion ------------------------------------------
// r,z,n gate order (torch GRUCell). No FMA contraction: separate mul/add ops
// exactly as the XLA elementwise graph evaluates them.
// If copy_dst != nullptr, also write h' there (step-0 h2 = h1 semantics).
__global__ void gru_gate_kernel(const float* __restrict__ gi,
                                const float* __restrict__ gh,
                                float* __restrict__ h,
                                float* __restrict__ copy_dst)
{
    int i = blockIdx.x * blockDim.x + threadIdx.x;   // over B*H
    int b = i >> 10;            // /H
    int j = i & (H - 1);
    size_t base = (size_t)b * G3H + j;
    float ir = gi[base], iz = gi[base + H], in_ = gi[base + 2 * H];
    float hr = gh[base], hz = gh[base + H], hn  = gh[base + 2 * H];
    // sigmoid(x) = 1 / (1 + exp(-x)), explicit rounding at each op
    float sr = __fadd_rn(ir, hr);
    float sz = __fadd_rn(iz, hz);
    float r  = __fdiv_rn(1.f, __fadd_rn(1.f, expf(-sr)));
    float zg = __fdiv_rn(1.f, __fadd_rn(1.f, expf(-sz)));
    float n  = tanhf(__fadd_rn(in_, __fmul_rn(r, hn)));
    float hv = __fadd_rn(__fmul_rn(__fsub_rn(1.f, zg), n),
                         __fmul_rn(zg, h[i]));
    h[i] = hv;
    if (copy_dst) copy_dst[i] = hv;
}

// ---------------- paired log-softmax + argmax + one-hot --------------------
// Reference order: shifted = x - max; lse = log(sum(exp(shifted)));
// logp = shifted - lse; argmax over the ROUNDED logp values (first-max -> 0).
// one_hot feedback written directly into g_inp[:, 0:256] (row stride KIN).
__global__ void softmax_kernel(const float* __restrict__ tmp,
                               float* __restrict__ inp,
                               float* __restrict__ dout, int t)
{
    int i = blockIdx.x * blockDim.x + threadIdx.x;   // over B*128
    int b = i >> 7;
    int f = i & 127;
    float a = tmp[(size_t)b * D + f];
    float c = tmp[(size_t)b * D + 128 + f];
    float m  = fmaxf(a, c);
    float sa = __fsub_rn(a, m);
    float sc = __fsub_rn(c, m);
    float lse = logf(__fadd_rn(expf(sa), expf(sc)));
    float la = __fsub_rn(sa, lse);
    float lc = __fsub_rn(sc, lse);
    size_t ob = (size_t)b * NSTEP * D + (size_t)t * D;
    dout[ob + f]       = la;
    dout[ob + 128 + f] = lc;
    int idx = (la >= lc) ? 0 : 1;     // argmax over logp, tie -> class 0
    inp[(size_t)b * KIN + 2 * f]     = (idx == 0) ? 1.f : 0.f;
    inp[(size_t)b * KIN + 2 * f + 1] = (idx == 1) ? 1.f : 0.f;
}

// inp[:, :256] = one-hot(last)=e_255, inp[:, 256:512] = z  (z half is static)
__global__ void init_inp_kernel(const float* __restrict__ z,
                                float* __restrict__ inp)
{
    int i = blockIdx.x * blockDim.x + threadIdx.x;   // over B*KIN
    int b = i >> 9;             // /KIN
    int j = i & (KIN - 1);
    float v;
    if (j < D) v = (j == D - 1) ? 1.f : 0.f;
    else       v = z[(size_t)b * L + (j - D)];
    inp[i] = v;
}

// ---------------- launch ---------------------------------------------------
extern "C" void kernel_launch(void* const* d_in, const int* in_sizes, int n_in,
                              void* d_out, int out_size)
{
    (void)in_sizes; (void)n_in; (void)out_size;
    const float* z      = (const float*)d_in[0];
    const float* W_init = (const float*)d_in[1];
    const float* b_init = (const float*)d_in[2];
    const float* W_ih1  = (const float*)d_in[3];   // [3072, 512]
    const float* W_hh1  = (const float*)d_in[4];   // [3072, 1024]
    const float* b_ih1  = (const float*)d_in[5];
    const float* b_hh1  = (const float*)d_in[6];
    const float* W_ih2  = (const float*)d_in[7];
    const float* W_hh2  = (const float*)d_in[8];
    const float* b_ih2  = (const float*)d_in[9];
    const float* b_hh2  = (const float*)d_in[10];
    const float* W_out  = (const float*)d_in[11];  // [256, 1024]
    const float* b_out  = (const float*)d_in[12];
    float* out = (float*)d_out;

    float *inp, *gi, *gh, *h1, *h2, *tb;
    cudaGetSymbolAddress((void**)&inp, g_inp);
    cudaGetSymbolAddress((void**)&gi,  g_gi);
    cudaGetSymbolAddress((void**)&gh,  g_gh);
    cudaGetSymbolAddress((void**)&h1,  g_h1);
    cudaGetSymbolAddress((void**)&h2,  g_h2);
    cudaGetSymbolAddress((void**)&tb,  g_tmp);

    const dim3 blk(256);
    const dim3 grid_big(G3H / BN, B / BM);   // N=3072
    const dim3 grid_h  (H   / BN, B / BM);   // N=1024
    const dim3 grid_d  (D   / BN, B / BM);   // N=256

    // Prologue: inp = [one_hot | z], h1 = tanh(z @ W_init^T + b_init)
    init_inp_kernel<<<(B * KIN) / 256, blk>>>(z, inp);
    gemm_kernel<1><<<grid_h, blk>>>(z, L, W_init, L, b_init, h1, H, L);

    for (int t = 0; t < NSTEP; t++) {
        // gi1 = concat(out, z) @ W_ih1^T + b_ih1   (single serial K=512 sum)
        gemm_kernel<0><<<grid_big, blk>>>(inp, KIN, W_ih1, KIN, b_ih1,
                                          gi, G3H, KIN);
        // gh1 = h1 @ W_hh1^T + b_hh1
        gemm_kernel<0><<<grid_big, blk>>>(h1, H, W_hh1, H, b_hh1,
                                          gh, G3H, H);
        gru_gate_kernel<<<(B * H) / 256, blk>>>(gi, gh, h1,
                                                (t == 0) ? h2 : nullptr);
        // gi2 = h1 @ W_ih2^T + b_ih2
        gemm_kernel<0><<<grid_big, blk>>>(h1, H, W_ih2, H, b_ih2,
                                          gi, G3H, H);
        // gh2 = h2 @ W_hh2^T + b_hh2
        gemm_kernel<0><<<grid_big, blk>>>(h2, H, W_hh2, H, b_hh2,
                                          gh, G3H, H);
        gru_gate_kernel<<<(B * H) / 256, blk>>>(gi, gh, h2, nullptr);
        // logits = h2 @ W_out^T + b_out
        gemm_kernel<0><<<grid_d, blk>>>(h2, H, W_out, H, b_out,
                                        tb, D, H);
        softmax_kernel<<<(B * 128) / 256, blk>>>(tb, inp, out, t);
    }
}

// round 8
// speedup vs baseline: 1.0881x; 1.0881x over previous
#include <cuda_runtime.h>
#include <math.h>

// R7 = R6 resubmission (R6 bench was an infra failure, change untested).
// Numerics identical to the passing R5: serial ascending-k fp32 FMA chain per
// output, post-sum bias, de-fused gates, reference-ordered log-softmax.
// Perf changes under test: 128x128 tiles, 8x8 microtiles (4+4 split layout),
// double-buffered smem, gi/gh paired into one launch via gridDim.z.

// Problem constants
#define B     2048
#define L     256
#define H     1024
#define D     256
#define NSTEP 64
#define G3H   (3*H)   // 3072
#define KIN   (D + L) // 512

// ---------------- scratch (device globals: allocation-free) ----------------
__device__ float g_inp [(size_t)B * KIN];
__device__ float g_gi  [(size_t)B * G3H];
__device__ float g_gh  [(size_t)B * G3H];
__device__ float g_h1  [(size_t)B * H];
__device__ float g_h2  [(size_t)B * H];
__device__ float g_tmp [(size_t)B * D];

// ============ big GEMM: C = A @ W^T + bias, paired via blockIdx.z ==========
// 128x128 tile, BK=16, 256 threads, 8x8 microtile split as rows {ty*4+i,
// 64+ty*4+i}, cols {tx*4+j, 64+tx*4+j}. Double-buffered smem.
// Per-output accumulation remains a SERIAL ascending-k FMA chain.
#define BM 128
#define BN 128
#define BK 16
#define NT 256

__global__ void __launch_bounds__(NT, 2) gemm_big_kernel(
    const float* __restrict__ A0, int lda0,
    const float* __restrict__ W0, int ldw0,
    const float* __restrict__ bias0, float* __restrict__ C0, int K0,
    const float* __restrict__ A1, int lda1,
    const float* __restrict__ W1, int ldw1,
    const float* __restrict__ bias1, float* __restrict__ C1, int K1,
    int N)
{
    __shared__ float As[2][BK][BM + 4];
    __shared__ float Bs[2][BK][BN + 4];

    const float *A, *W, *bias; float* C; int lda, ldw, K;
    if (blockIdx.z == 0) { A=A0; lda=lda0; W=W0; ldw=ldw0; bias=bias0; C=C0; K=K0; }
    else                 { A=A1; lda=lda1; W=W1; ldw=ldw1; bias=bias1; C=C1; K=K1; }

    const int tid = threadIdx.x;
    const int tx  = tid & 15;
    const int ty  = tid >> 4;
    const int m0  = blockIdx.y * BM;
    const int n0  = blockIdx.x * BN;

    float acc[8][8];
    #pragma unroll
    for (int i = 0; i < 8; i++)
        #pragma unroll
        for (int j = 0; j < 8; j++) acc[i][j] = 0.f;

    float4 pa[2], pb[2];

    // global fetch of tile kt into registers
    auto fetch_g = [&](int kt) {
        #pragma unroll
        for (int l = 0; l < 2; l++) {
            int idx4 = tid + l * NT;
            int r = idx4 >> 2, c4 = idx4 & 3;
            pa[l] = *reinterpret_cast<const float4*>(
                A + (size_t)(m0 + r) * lda + kt + c4 * 4);
            pb[l] = *reinterpret_cast<const float4*>(
                W + (size_t)(n0 + r) * ldw + kt + c4 * 4);
        }
    };
    // store registers into smem buffer (transposed to [k][row])
    auto store_s = [&](int buf) {
        #pragma unroll
        for (int l = 0; l < 2; l++) {
            int idx4 = tid + l * NT;
            int r = idx4 >> 2, c4 = idx4 & 3;
            As[buf][c4*4+0][r] = pa[l].x; As[buf][c4*4+1][r] = pa[l].y;
            As[buf][c4*4+2][r] = pa[l].z; As[buf][c4*4+3][r] = pa[l].w;
            Bs[buf][c4*4+0][r] = pb[l].x; Bs[buf][c4*4+1][r] = pb[l].y;
            Bs[buf][c4*4+2][r] = pb[l].z; Bs[buf][c4*4+3][r] = pb[l].w;
        }
    };

    const int ntiles = K / BK;
    fetch_g(0);
    store_s(0);
    __syncthreads();

    int cur = 0;
    for (int t = 0; t < ntiles; t++) {
        if (t + 1 < ntiles) fetch_g((t + 1) * BK);

        #pragma unroll
        for (int k = 0; k < BK; k++) {
            float4 a0 = *reinterpret_cast<const float4*>(&As[cur][k][ty * 4]);
            float4 a1 = *reinterpret_cast<const float4*>(&As[cur][k][64 + ty * 4]);
            float4 b0 = *reinterpret_cast<const float4*>(&Bs[cur][k][tx * 4]);
            float4 b1 = *reinterpret_cast<const float4*>(&Bs[cur][k][64 + tx * 4]);
            float av[8] = {a0.x, a0.y, a0.z, a0.w, a1.x, a1.y, a1.z, a1.w};
            float bv[8] = {b0.x, b0.y, b0.z, b0.w, b1.x, b1.y, b1.z, b1.w};
            #pragma unroll
            for (int i = 0; i < 8; i++)
                #pragma unroll
                for (int j = 0; j < 8; j++)
                    acc[i][j] = fmaf(av[i], bv[j], acc[i][j]);
        }

        if (t + 1 < ntiles) {
            store_s(cur ^ 1);
            __syncthreads();
            cur ^= 1;
        }
    }

    // Epilogue: bias after full K sum (reference order).
    float4 bb0 = *reinterpret_cast<const float4*>(bias + n0 + tx * 4);
    float4 bb1 = *reinterpret_cast<const float4*>(bias + n0 + 64 + tx * 4);

    #pragma unroll
    for (int i = 0; i < 8; i++) {
        int m = m0 + ((i < 4) ? (ty * 4 + i) : (64 + ty * 4 + (i - 4)));
        size_t off = (size_t)m * N + n0;
        float4 v0 = make_float4(__fadd_rn(acc[i][0], bb0.x),
                                __fadd_rn(acc[i][1], bb0.y),
                                __fadd_rn(acc[i][2], bb0.z),
                                __fadd_rn(acc[i][3], bb0.w));
        float4 v1 = make_float4(__fadd_rn(acc[i][4], bb1.x),
                                __fadd_rn(acc[i][5], bb1.y),
                                __fadd_rn(acc[i][6], bb1.z),
                                __fadd_rn(acc[i][7], bb1.w));
        *reinterpret_cast<float4*>(C + off + tx * 4)      = v0;
        *reinterpret_cast<float4*>(C + off + 64 + tx * 4) = v1;
    }
}

// ============ small GEMM (prologue h1, W_out) — unchanged from R5 ==========
#define SBM 128
#define SBN 64
#define SBK 16

template<int ACT>
__global__ void __launch_bounds__(256, 4) gemm_kernel(
    const float* __restrict__ A, int lda,
    const float* __restrict__ W, int ldw,
    const float* __restrict__ bias,
    float* __restrict__ C,
    int N, int K)
{
    __shared__ float As[SBK][SBM + 4];
    __shared__ float Bs[SBK][SBN + 4];

    const int tid = threadIdx.x;
    const int tx  = tid & 15;
    const int ty  = tid >> 4;
    const int m0  = blockIdx.y * SBM;
    const int n0  = blockIdx.x * SBN;

    float acc[8][4];
    #pragma unroll
    for (int i = 0; i < 8; i++)
        #pragma unroll
        for (int j = 0; j < 4; j++) acc[i][j] = 0.f;

    for (int kt = 0; kt < K; kt += SBK) {
        #pragma unroll
        for (int l = 0; l < 2; l++) {
            int idx4 = tid + l * 256;
            int r = idx4 >> 2, c4 = idx4 & 3;
            float4 v = *reinterpret_cast<const float4*>(
                A + (size_t)(m0 + r) * lda + kt + c4 * 4);
            As[c4*4+0][r] = v.x; As[c4*4+1][r] = v.y;
            As[c4*4+2][r] = v.z; As[c4*4+3][r] = v.w;
        }
        {
            int r = tid >> 2, c4 = tid & 3;
            float4 v = *reinterpret_cast<const float4*>(
                W + (size_t)(n0 + r) * ldw + kt + c4 * 4);
            Bs[c4*4+0][r] = v.x; Bs[c4*4+1][r] = v.y;
            Bs[c4*4+2][r] = v.z; Bs[c4*4+3][r] = v.w;
        }
        __syncthreads();

        #pragma unroll
        for (int k = 0; k < SBK; k++) {
            float4 a0 = *reinterpret_cast<const float4*>(&As[k][ty * 8]);
            float4 a1 = *reinterpret_cast<const float4*>(&As[k][ty * 8 + 4]);
            float4 b0 = *reinterpret_cast<const float4*>(&Bs[k][tx * 4]);
            float av[8] = {a0.x, a0.y, a0.z, a0.w, a1.x, a1.y, a1.z, a1.w};
            float bv[4] = {b0.x, b0.y, b0.z, b0.w};
            #pragma unroll
            for (int i = 0; i < 8; i++)
                #pragma unroll
                for (int j = 0; j < 4; j++)
                    acc[i][j] = fmaf(av[i], bv[j], acc[i][j]);
        }
        __syncthreads();
    }

    float4 b4 = make_float4(0.f, 0.f, 0.f, 0.f);
    if (bias) b4 = *reinterpret_cast<const float4*>(bias + n0 + tx * 4);

    #pragma unroll
    for (int i = 0; i < 8; i++) {
        int m = m0 + ty * 8 + i;
        size_t off = (size_t)m * N + n0 + tx * 4;
        float4 v = make_float4(__fadd_rn(acc[i][0], b4.x),
                               __fadd_rn(acc[i][1], b4.y),
                               __fadd_rn(acc[i][2], b4.z),
                               __fadd_rn(acc[i][3], b4.w));
        if (ACT == 1) {
            v.x = tanhf(v.x); v.y = tanhf(v.y);
            v.z = tanhf(v.z); v.w = tanhf(v.w);
        }
        *reinterpret_cast<float4*>(C + off) = v;
    }
}

// ---------------- GRU gate fusion (unchanged) ------------------------------
__global__ void gru_gate_kernel(const float* __restrict__ gi,
                                const float* __restrict__ gh,
                                float* __restrict__ h,
                                float* __restrict__ copy_dst)
{
    int i = blockIdx.x * blockDim.x + threadIdx.x;
    int b = i >> 10;
    int j = i & (H - 1);
    size_t base = (size_t)b * G3H + j;
    float ir = gi[base], iz = gi[base + H], in_ = gi[base + 2 * H];
    float hr = gh[base], hz = gh[base + H], hn  = gh[base + 2 * H];
    float sr = __fadd_rn(ir, hr);
    float sz = __fadd_rn(iz, hz);
    float r  = __fdiv_rn(1.f, __fadd_rn(1.f, expf(-sr)));
    float zg = __fdiv_rn(1.f, __fadd_rn(1.f, expf(-sz)));
    float n  = tanhf(__fadd_rn(in_, __fmul_rn(r, hn)));
    float hv = __fadd_rn(__fmul_rn(__fsub_rn(1.f, zg), n),
                         __fmul_rn(zg, h[i]));
    h[i] = hv;
    if (copy_dst) copy_dst[i] = hv;
}

// ---------------- paired log-softmax + argmax + one-hot (unchanged) --------
__global__ void softmax_kernel(const float* __restrict__ tmp,
                               float* __restrict__ inp,
                               float* __restrict__ dout, int t)
{
    int i = blockIdx.x * blockDim.x + threadIdx.x;
    int b = i >> 7;
    int f = i & 127;
    float a = tmp[(size_t)b * D + f];
    float c = tmp[(size_t)b * D + 128 + f];
    float m  = fmaxf(a, c);
    float sa = __fsub_rn(a, m);
    float sc = __fsub_rn(c, m);
    float lse = logf(__fadd_rn(expf(sa), expf(sc)));
    float la = __fsub_rn(sa, lse);
    float lc = __fsub_rn(sc, lse);
    size_t ob = (size_t)b * NSTEP * D + (size_t)t * D;
    dout[ob + f]       = la;
    dout[ob + 128 + f] = lc;
    int idx = (la >= lc) ? 0 : 1;
    inp[(size_t)b * KIN + 2 * f]     = (idx == 0) ? 1.f : 0.f;
    inp[(size_t)b * KIN + 2 * f + 1] = (idx == 1) ? 1.f : 0.f;
}

__global__ void init_inp_kernel(const float* __restrict__ z,
                                float* __restrict__ inp)
{
    int i = blockIdx.x * blockDim.x + threadIdx.x;
    int b = i >> 9;
    int j = i & (KIN - 1);
    float v;
    if (j < D) v = (j == D - 1) ? 1.f : 0.f;
    else       v = z[(size_t)b * L + (j - D)];
    inp[i] = v;
}

// ---------------- launch ---------------------------------------------------
extern "C" void kernel_launch(void* const* d_in, const int* in_sizes, int n_in,
                              void* d_out, int out_size)
{
    (void)in_sizes; (void)n_in; (void)out_size;
    const float* z      = (const float*)d_in[0];
    const float* W_init = (const float*)d_in[1];
    const float* b_init = (const float*)d_in[2];
    const float* W_ih1  = (const float*)d_in[3];   // [3072, 512]
    const float* W_hh1  = (const float*)d_in[4];   // [3072, 1024]
    const float* b_ih1  = (const float*)d_in[5];
    const float* b_hh1  = (const float*)d_in[6];
    const float* W_ih2  = (const float*)d_in[7];
    const float* W_hh2  = (const float*)d_in[8];
    const float* b_ih2  = (const float*)d_in[9];
    const float* b_hh2  = (const float*)d_in[10];
    const float* W_out  = (const float*)d_in[11];  // [256, 1024]
    const float* b_out  = (const float*)d_in[12];
    float* out = (float*)d_out;

    float *inp, *gi, *gh, *h1, *h2, *tb;
    cudaGetSymbolAddress((void**)&inp, g_inp);
    cudaGetSymbolAddress((void**)&gi,  g_gi);
    cudaGetSymbolAddress((void**)&gh,  g_gh);
    cudaGetSymbolAddress((void**)&h1,  g_h1);
    cudaGetSymbolAddress((void**)&h2,  g_h2);
    cudaGetSymbolAddress((void**)&tb,  g_tmp);

    const dim3 blk(256);
    const dim3 grid_pair(G3H / BN, B / BM, 2);    // 24 x 16 x 2
    const dim3 grid_h  (H / SBN, B / SBM);        // prologue
    const dim3 grid_d  (D / SBN, B / SBM);        // W_out

    // Prologue: inp = [one_hot | z], h1 = tanh(z @ W_init^T + b_init)
    init_inp_kernel<<<(B * KIN) / 256, blk>>>(z, inp);
    gemm_kernel<1><<<grid_h, blk>>>(z, L, W_init, L, b_init, h1, H, L);

    for (int t = 0; t < NSTEP; t++) {
        // layer 1: gi1 (K=512, concat input) + gh1 (K=1024) in one launch
        gemm_big_kernel<<<grid_pair, blk>>>(
            inp, KIN, W_ih1, KIN, b_ih1, gi, KIN,
            h1,  H,   W_hh1, H,   b_hh1, gh, H,
            G3H);
        gru_gate_kernel<<<(B * H) / 256, blk>>>(gi, gh, h1,
                                                (t == 0) ? h2 : nullptr);
        // layer 2: gi2 + gh2 in one launch (both K=1024)
        gemm_big_kernel<<<grid_pair, blk>>>(
            h1, H, W_ih2, H, b_ih2, gi, H,
            h2, H, W_hh2, H, b_hh2, gh, H,
            G3H);
        gru_gate_kernel<<<(B * H) / 256, blk>>>(gi, gh, h2, nullptr);
        // logits = h2 @ W_out^T + b_out
        gemm_kernel<0><<<grid_d, blk>>>(h2, H, W_out, H, b_out, tb, D, H);
        softmax_kernel<<<(B * 128) / 256, blk>>>(tb, inp, out, t);
    }
}

// round 10
// speedup vs baseline: 1.1455x; 1.0527x over previous
#include <cuda_runtime.h>
#include <math.h>

// R9 = R8 resubmission (R8 bench was an infra failure, change-set untested).
// Numerics identical to passing R7: serial ascending-k fp32 FMA chain,
// post-sum bias, de-fused gates, reference-ordered log-softmax.
// Under test: (1) dummy kernel at launch 0 so ncu -s 5 captures gemm_big;
// (2) heavy-K GEMM at z=0 in pair launches (tail packing);
// (3) float4-vectorized gate kernel.

// Problem constants
#define B     2048
#define L     256
#define H     1024
#define D     256
#define NSTEP 64
#define G3H   (3*H)   // 3072
#define KIN   (D + L) // 512

// ---------------- scratch (device globals: allocation-free) ----------------
__device__ float g_inp [(size_t)B * KIN];
__device__ float g_gi  [(size_t)B * G3H];
__device__ float g_gh  [(size_t)B * G3H];
__device__ float g_h1  [(size_t)B * H];
__device__ float g_h2  [(size_t)B * H];
__device__ float g_tmp [(size_t)B * D];

// no-op: aligns ncu's -s 5 skip onto a gemm_big launch
__global__ void dummy_kernel() {}

// ============ big GEMM: C = A @ W^T + bias, paired via blockIdx.z ==========
// 128x128 tile, BK=16, 256 threads, 8x8 microtile (4+4 split), double-buffered.
// Per-output accumulation is a SERIAL ascending-k FMA chain (invariant).
#define BM 128
#define BN 128
#define BK 16
#define NT 256

__global__ void __launch_bounds__(NT, 2) gemm_big_kernel(
    const float* __restrict__ A0, int lda0,
    const float* __restrict__ W0, int ldw0,
    const float* __restrict__ bias0, float* __restrict__ C0, int K0,
    const float* __restrict__ A1, int lda1,
    const float* __restrict__ W1, int ldw1,
    const float* __restrict__ bias1, float* __restrict__ C1, int K1,
    int N)
{
    __shared__ float As[2][BK][BM + 4];
    __shared__ float Bs[2][BK][BN + 4];

    const float *A, *W, *bias; float* C; int lda, ldw, K;
    if (blockIdx.z == 0) { A=A0; lda=lda0; W=W0; ldw=ldw0; bias=bias0; C=C0; K=K0; }
    else                 { A=A1; lda=lda1; W=W1; ldw=ldw1; bias=bias1; C=C1; K=K1; }

    const int tid = threadIdx.x;
    const int tx  = tid & 15;
    const int ty  = tid >> 4;
    const int m0  = blockIdx.y * BM;
    const int n0  = blockIdx.x * BN;

    float acc[8][8];
    #pragma unroll
    for (int i = 0; i < 8; i++)
        #pragma unroll
        for (int j = 0; j < 8; j++) acc[i][j] = 0.f;

    float4 pa[2], pb[2];

    auto fetch_g = [&](int kt) {
        #pragma unroll
        for (int l = 0; l < 2; l++) {
            int idx4 = tid + l * NT;
            int r = idx4 >> 2, c4 = idx4 & 3;
            pa[l] = *reinterpret_cast<const float4*>(
                A + (size_t)(m0 + r) * lda + kt + c4 * 4);
            pb[l] = *reinterpret_cast<const float4*>(
                W + (size_t)(n0 + r) * ldw + kt + c4 * 4);
        }
    };
    auto store_s = [&](int buf) {
        #pragma unroll
        for (int l = 0; l < 2; l++) {
            int idx4 = tid + l * NT;
            int r = idx4 >> 2, c4 = idx4 & 3;
            As[buf][c4*4+0][r] = pa[l].x; As[buf][c4*4+1][r] = pa[l].y;
            As[buf][c4*4+2][r] = pa[l].z; As[buf][c4*4+3][r] = pa[l].w;
            Bs[buf][c4*4+0][r] = pb[l].x; Bs[buf][c4*4+1][r] = pb[l].y;
            Bs[buf][c4*4+2][r] = pb[l].z; Bs[buf][c4*4+3][r] = pb[l].w;
        }
    };

    const int ntiles = K / BK;
    fetch_g(0);
    store_s(0);
    __syncthreads();

    int cur = 0;
    for (int t = 0; t < ntiles; t++) {
        if (t + 1 < ntiles) fetch_g((t + 1) * BK);

        #pragma unroll
        for (int k = 0; k < BK; k++) {
            float4 a0 = *reinterpret_cast<const float4*>(&As[cur][k][ty * 4]);
            float4 a1 = *reinterpret_cast<const float4*>(&As[cur][k][64 + ty * 4]);
            float4 b0 = *reinterpret_cast<const float4*>(&Bs[cur][k][tx * 4]);
            float4 b1 = *reinterpret_cast<const float4*>(&Bs[cur][k][64 + tx * 4]);
            float av[8] = {a0.x, a0.y, a0.z, a0.w, a1.x, a1.y, a1.z, a1.w};
            float bv[8] = {b0.x, b0.y, b0.z, b0.w, b1.x, b1.y, b1.z, b1.w};
            #pragma unroll
            for (int i = 0; i < 8; i++)
                #pragma unroll
                for (int j = 0; j < 8; j++)
                    acc[i][j] = fmaf(av[i], bv[j], acc[i][j]);
        }

        if (t + 1 < ntiles) {
            store_s(cur ^ 1);
            __syncthreads();
            cur ^= 1;
        }
    }

    float4 bb0 = *reinterpret_cast<const float4*>(bias + n0 + tx * 4);
    float4 bb1 = *reinterpret_cast<const float4*>(bias + n0 + 64 + tx * 4);

    #pragma unroll
    for (int i = 0; i < 8; i++) {
        int m = m0 + ((i < 4) ? (ty * 4 + i) : (64 + ty * 4 + (i - 4)));
        size_t off = (size_t)m * N + n0;
        float4 v0 = make_float4(__fadd_rn(acc[i][0], bb0.x),
                                __fadd_rn(acc[i][1], bb0.y),
                                __fadd_rn(acc[i][2], bb0.z),
                                __fadd_rn(acc[i][3], bb0.w));
        float4 v1 = make_float4(__fadd_rn(acc[i][4], bb1.x),
                                __fadd_rn(acc[i][5], bb1.y),
                                __fadd_rn(acc[i][6], bb1.z),
                                __fadd_rn(acc[i][7], bb1.w));
        *reinterpret_cast<float4*>(C + off + tx * 4)      = v0;
        *reinterpret_cast<float4*>(C + off + 64 + tx * 4) = v1;
    }
}

// ============ small GEMM (prologue h1, W_out) — unchanged ==================
#define SBM 128
#define SBN 64
#define SBK 16

template<int ACT>
__global__ void __launch_bounds__(256, 4) gemm_kernel(
    const float* __restrict__ A, int lda,
    const float* __restrict__ W, int ldw,
    const float* __restrict__ bias,
    float* __restrict__ C,
    int N, int K)
{
    __shared__ float As[SBK][SBM + 4];
    __shared__ float Bs[SBK][SBN + 4];

    const int tid = threadIdx.x;
    const int tx  = tid & 15;
    const int ty  = tid >> 4;
    const int m0  = blockIdx.y * SBM;
    const int n0  = blockIdx.x * SBN;

    float acc[8][4];
    #pragma unroll
    for (int i = 0; i < 8; i++)
        #pragma unroll
        for (int j = 0; j < 4; j++) acc[i][j] = 0.f;

    for (int kt = 0; kt < K; kt += SBK) {
        #pragma unroll
        for (int l = 0; l < 2; l++) {
            int idx4 = tid + l * 256;
            int r = idx4 >> 2, c4 = idx4 & 3;
            float4 v = *reinterpret_cast<const float4*>(
                A + (size_t)(m0 + r) * lda + kt + c4 * 4);
            As[c4*4+0][r] = v.x; As[c4*4+1][r] = v.y;
            As[c4*4+2][r] = v.z; As[c4*4+3][r] = v.w;
        }
        {
            int r = tid >> 2, c4 = tid & 3;
            float4 v = *reinterpret_cast<const float4*>(
                W + (size_t)(n0 + r) * ldw + kt + c4 * 4);
            Bs[c4*4+0][r] = v.x; Bs[c4*4+1][r] = v.y;
            Bs[c4*4+2][r] = v.z; Bs[c4*4+3][r] = v.w;
        }
        __syncthreads();

        #pragma unroll
        for (int k = 0; k < SBK; k++) {
            float4 a0 = *reinterpret_cast<const float4*>(&As[k][ty * 8]);
            float4 a1 = *reinterpret_cast<const float4*>(&As[k][ty * 8 + 4]);
            float4 b0 = *reinterpret_cast<const float4*>(&Bs[k][tx * 4]);
            float av[8] = {a0.x, a0.y, a0.z, a0.w, a1.x, a1.y, a1.z, a1.w};
            float bv[4] = {b0.x, b0.y, b0.z, b0.w};
            #pragma unroll
            for (int i = 0; i < 8; i++)
                #pragma unroll
                for (int j = 0; j < 4; j++)
                    acc[i][j] = fmaf(av[i], bv[j], acc[i][j]);
        }
        __syncthreads();
    }

    float4 b4 = make_float4(0.f, 0.f, 0.f, 0.f);
    if (bias) b4 = *reinterpret_cast<const float4*>(bias + n0 + tx * 4);

    #pragma unroll
    for (int i = 0; i < 8; i++) {
        int m = m0 + ty * 8 + i;
        size_t off = (size_t)m * N + n0 + tx * 4;
        float4 v = make_float4(__fadd_rn(acc[i][0], b4.x),
                               __fadd_rn(acc[i][1], b4.y),
                               __fadd_rn(acc[i][2], b4.z),
                               __fadd_rn(acc[i][3], b4.w));
        if (ACT == 1) {
            v.x = tanhf(v.x); v.y = tanhf(v.y);
            v.z = tanhf(v.z); v.w = tanhf(v.w);
        }
        *reinterpret_cast<float4*>(C + off) = v;
    }
}

// ---------------- GRU gate fusion (float4-vectorized) ----------------------
// Per-element math identical to R7 (de-fused, explicit rounding).
__global__ void gru_gate_kernel(const float* __restrict__ gi,
                                const float* __restrict__ gh,
                                float* __restrict__ h,
                                float* __restrict__ copy_dst)
{
    int q = blockIdx.x * blockDim.x + threadIdx.x;   // over B*H/4
    int b = q >> 8;                  // / (H/4)
    int j4 = (q & 255) << 2;         // element offset within row, mult of 4
    size_t base = (size_t)b * G3H + j4;
    size_t hoff = (size_t)b * H + j4;

    float4 ir4 = *reinterpret_cast<const float4*>(gi + base);
    float4 iz4 = *reinterpret_cast<const float4*>(gi + base + H);
    float4 in4 = *reinterpret_cast<const float4*>(gi + base + 2 * H);
    float4 hr4 = *reinterpret_cast<const float4*>(gh + base);
    float4 hz4 = *reinterpret_cast<const float4*>(gh + base + H);
    float4 hn4 = *reinterpret_cast<const float4*>(gh + base + 2 * H);
    float4 h4  = *reinterpret_cast<const float4*>(h + hoff);

    float hv[4];
    const float ir[4] = {ir4.x, ir4.y, ir4.z, ir4.w};
    const float iz[4] = {iz4.x, iz4.y, iz4.z, iz4.w};
    const float in_[4] = {in4.x, in4.y, in4.z, in4.w};
    const float hr[4] = {hr4.x, hr4.y, hr4.z, hr4.w};
    const float hz[4] = {hz4.x, hz4.y, hz4.z, hz4.w};
    const float hn[4] = {hn4.x, hn4.y, hn4.z, hn4.w};
    const float hp[4] = {h4.x, h4.y, h4.z, h4.w};

    #pragma unroll
    for (int e = 0; e < 4; e++) {
        float sr = __fadd_rn(ir[e], hr[e]);
        float sz = __fadd_rn(iz[e], hz[e]);
        float r  = __fdiv_rn(1.f, __fadd_rn(1.f, expf(-sr)));
        float zg = __fdiv_rn(1.f, __fadd_rn(1.f, expf(-sz)));
        float n  = tanhf(__fadd_rn(in_[e], __fmul_rn(r, hn[e])));
        hv[e] = __fadd_rn(__fmul_rn(__fsub_rn(1.f, zg), n),
                          __fmul_rn(zg, hp[e]));
    }
    float4 hv4 = make_float4(hv[0], hv[1], hv[2], hv[3]);
    *reinterpret_cast<float4*>(h + hoff) = hv4;
    if (copy_dst) *reinterpret_cast<float4*>(copy_dst + hoff) = hv4;
}

// ---------------- paired log-softmax + argmax + one-hot (unchanged) --------
__global__ void softmax_kernel(const float* __restrict__ tmp,
                               float* __restrict__ inp,
                               float* __restrict__ dout, int t)
{
    int i = blockIdx.x * blockDim.x + threadIdx.x;
    int b = i >> 7;
    int f = i & 127;
    float a = tmp[(size_t)b * D + f];
    float c = tmp[(size_t)b * D + 128 + f];
    float m  = fmaxf(a, c);
    float sa = __fsub_rn(a, m);
    float sc = __fsub_rn(c, m);
    float lse = logf(__fadd_rn(expf(sa), expf(sc)));
    float la = __fsub_rn(sa, lse);
    float lc = __fsub_rn(sc, lse);
    size_t ob = (size_t)b * NSTEP * D + (size_t)t * D;
    dout[ob + f]       = la;
    dout[ob + 128 + f] = lc;
    int idx = (la >= lc) ? 0 : 1;
    inp[(size_t)b * KIN + 2 * f]     = (idx == 0) ? 1.f : 0.f;
    inp[(size_t)b * KIN + 2 * f + 1] = (idx == 1) ? 1.f : 0.f;
}

__global__ void init_inp_kernel(const float* __restrict__ z,
                                float* __restrict__ inp)
{
    int i = blockIdx.x * blockDim.x + threadIdx.x;
    int b = i >> 9;
    int j = i & (KIN - 1);
    float v;
    if (j < D) v = (j == D - 1) ? 1.f : 0.f;
    else       v = z[(size_t)b * L + (j - D)];
    inp[i] = v;
}

// ---------------- launch ---------------------------------------------------
extern "C" void kernel_launch(void* const* d_in, const int* in_sizes, int n_in,
                              void* d_out, int out_size)
{
    (void)in_sizes; (void)n_in; (void)out_size;
    const float* z      = (const float*)d_in[0];
    const float* W_init = (const float*)d_in[1];
    const float* b_init = (const float*)d_in[2];
    const float* W_ih1  = (const float*)d_in[3];   // [3072, 512]
    const float* W_hh1  = (const float*)d_in[4];   // [3072, 1024]
    const float* b_ih1  = (const float*)d_in[5];
    const float* b_hh1  = (const float*)d_in[6];
    const float* W_ih2  = (const float*)d_in[7];
    const float* W_hh2  = (const float*)d_in[8];
    const float* b_ih2  = (const float*)d_in[9];
    const float* b_hh2  = (const float*)d_in[10];
    const float* W_out  = (const float*)d_in[11];  // [256, 1024]
    const float* b_out  = (const float*)d_in[12];
    float* out = (float*)d_out;

    float *inp, *gi, *gh, *h1, *h2, *tb;
    cudaGetSymbolAddress((void**)&inp, g_inp);
    cudaGetSymbolAddress((void**)&gi,  g_gi);
    cudaGetSymbolAddress((void**)&gh,  g_gh);
    cudaGetSymbolAddress((void**)&h1,  g_h1);
    cudaGetSymbolAddress((void**)&h2,  g_h2);
    cudaGetSymbolAddress((void**)&tb,  g_tmp);

    const dim3 blk(256);
    const dim3 grid_pair(G3H / BN, B / BM, 2);    // 24 x 16 x 2
    const dim3 grid_h  (H / SBN, B / SBM);
    const dim3 grid_d  (D / SBN, B / SBM);

    // launch 0: dummy (aligns ncu -s 5 onto pair2 = gemm_big)
    dummy_kernel<<<1, 32>>>();
    // Prologue
    init_inp_kernel<<<(B * KIN) / 256, blk>>>(z, inp);
    gemm_kernel<1><<<grid_h, blk>>>(z, L, W_init, L, b_init, h1, H, L);

    for (int t = 0; t < NSTEP; t++) {
        // layer 1: HEAVY gh1 (K=1024) at z=0 so light gi1 (K=512) fills tail
        gemm_big_kernel<<<grid_pair, blk>>>(
            h1,  H,   W_hh1, H,   b_hh1, gh, H,
            inp, KIN, W_ih1, KIN, b_ih1, gi, KIN,
            G3H);
        gru_gate_kernel<<<(B * H / 4) / 256, blk>>>(gi, gh, h1,
                                                    (t == 0) ? h2 : nullptr);
        // layer 2: gi2 + gh2 (both K=1024)
        gemm_big_kernel<<<grid_pair, blk>>>(
            h1, H, W_ih2, H, b_ih2, gi, H,
            h2, H, W_hh2, H, b_hh2, gh, H,
            G3H);
        gru_gate_kernel<<<(B * H / 4) / 256, blk>>>(gi, gh, h2, nullptr);
        // logits
        gemm_kernel<0><<<grid_d, blk>>>(h2, H, W_out, H, b_out, tb, D, H);
        softmax_kernel<<<(B * 128) / 256, blk>>>(tb, inp, out, t);
    }
}

// round 11
// speedup vs baseline: 1.2106x; 1.0568x over previous
#include <cuda_runtime.h>
#include <math.h>

// R10: numerics invariant (serial ascending-k fp32 FMA chain per output,
// post-sum bias, de-fused gates, reference-ordered log-softmax).
// Changes: (1) W_out retiled 32x64 -> 256 blocks (was 64, 22% chip);
// (2) gemm_big: explicit fragment double-buffer + smem stores interleaved
// into the FMA stream; (3) everything else from R9 kept.

// Problem constants
#define B     2048
#define L     256
#define H     1024
#define D     256
#define NSTEP 64
#define G3H   (3*H)   // 3072
#define KIN   (D + L) // 512

// ---------------- scratch (device globals: allocation-free) ----------------
__device__ float g_inp [(size_t)B * KIN];
__device__ float g_gi  [(size_t)B * G3H];
__device__ float g_gh  [(size_t)B * G3H];
__device__ float g_h1  [(size_t)B * H];
__device__ float g_h2  [(size_t)B * H];
__device__ float g_tmp [(size_t)B * D];

// no-op: aligns ncu's -s 5 skip onto the pair2 gemm_big launch
__global__ void dummy_kernel() {}

// ============ big GEMM: C = A @ W^T + bias, paired via blockIdx.z ==========
// 128x128 tile, BK=16, 256 threads, 8x8 microtile (4+4 split), double-buffered
// smem, explicit frag ping-pong, stores interleaved at k=9/k=13.
// Per-output accumulation is a SERIAL ascending-k FMA chain (invariant).
#define BM 128
#define BN 128
#define BK 16
#define NT 256

__global__ void __launch_bounds__(NT, 2) gemm_big_kernel(
    const float* __restrict__ A0, int lda0,
    const float* __restrict__ W0, int ldw0,
    const float* __restrict__ bias0, float* __restrict__ C0, int K0,
    const float* __restrict__ A1, int lda1,
    const float* __restrict__ W1, int ldw1,
    const float* __restrict__ bias1, float* __restrict__ C1, int K1,
    int N)
{
    __shared__ float As[2][BK][BM + 4];
    __shared__ float Bs[2][BK][BN + 4];

    const float *A, *W, *bias; float* C; int lda, ldw, K;
    if (blockIdx.z == 0) { A=A0; lda=lda0; W=W0; ldw=ldw0; bias=bias0; C=C0; K=K0; }
    else                 { A=A1; lda=lda1; W=W1; ldw=ldw1; bias=bias1; C=C1; K=K1; }

    const int tid = threadIdx.x;
    const int tx  = tid & 15;
    const int ty  = tid >> 4;
    const int m0  = blockIdx.y * BM;
    const int n0  = blockIdx.x * BN;
    const int r0  = tid >> 2;       // load row (l=0); l=1 adds 64
    const int c4  = tid & 3;        // load k-chunk (4 floats)

    const float* Ap = A + (size_t)(m0 + r0) * lda + c4 * 4;
    const float* Wp = W + (size_t)(n0 + r0) * ldw + c4 * 4;

    float acc[8][8];
    #pragma unroll
    for (int i = 0; i < 8; i++)
        #pragma unroll
        for (int j = 0; j < 8; j++) acc[i][j] = 0.f;

    float4 pa[2], pb[2];
    int cur = 0;

    auto fetchA = [&](int kt) {
        pa[0] = *reinterpret_cast<const float4*>(Ap + kt);
        pa[1] = *reinterpret_cast<const float4*>(Ap + (size_t)64 * lda + kt);
    };
    auto fetchB = [&](int kt) {
        pb[0] = *reinterpret_cast<const float4*>(Wp + kt);
        pb[1] = *reinterpret_cast<const float4*>(Wp + (size_t)64 * ldw + kt);
    };
    auto storeA = [&](int buf) {
        As[buf][c4*4+0][r0] = pa[0].x; As[buf][c4*4+1][r0] = pa[0].y;
        As[buf][c4*4+2][r0] = pa[0].z; As[buf][c4*4+3][r0] = pa[0].w;
        As[buf][c4*4+0][r0+64] = pa[1].x; As[buf][c4*4+1][r0+64] = pa[1].y;
        As[buf][c4*4+2][r0+64] = pa[1].z; As[buf][c4*4+3][r0+64] = pa[1].w;
    };
    auto storeB = [&](int buf) {
        Bs[buf][c4*4+0][r0] = pb[0].x; Bs[buf][c4*4+1][r0] = pb[0].y;
        Bs[buf][c4*4+2][r0] = pb[0].z; Bs[buf][c4*4+3][r0] = pb[0].w;
        Bs[buf][c4*4+0][r0+64] = pb[1].x; Bs[buf][c4*4+1][r0+64] = pb[1].y;
        Bs[buf][c4*4+2][r0+64] = pb[1].z; Bs[buf][c4*4+3][r0+64] = pb[1].w;
    };

    float a_fr[2][8], b_fr[2][8];
    auto load_frag = [&](int k, int s) {
        float4 a0 = *reinterpret_cast<const float4*>(&As[cur][k][ty * 4]);
        float4 a1 = *reinterpret_cast<const float4*>(&As[cur][k][64 + ty * 4]);
        float4 b0 = *reinterpret_cast<const float4*>(&Bs[cur][k][tx * 4]);
        float4 b1 = *reinterpret_cast<const float4*>(&Bs[cur][k][64 + tx * 4]);
        a_fr[s][0]=a0.x; a_fr[s][1]=a0.y; a_fr[s][2]=a0.z; a_fr[s][3]=a0.w;
        a_fr[s][4]=a1.x; a_fr[s][5]=a1.y; a_fr[s][6]=a1.z; a_fr[s][7]=a1.w;
        b_fr[s][0]=b0.x; b_fr[s][1]=b0.y; b_fr[s][2]=b0.z; b_fr[s][3]=b0.w;
        b_fr[s][4]=b1.x; b_fr[s][5]=b1.y; b_fr[s][6]=b1.z; b_fr[s][7]=b1.w;
    };

    const int ntiles = K / BK;
    fetchA(0); fetchB(0);
    storeA(0); storeB(0);
    __syncthreads();

    for (int t = 0; t < ntiles; t++) {
        const bool hn = (t + 1 < ntiles);
        if (hn) { fetchA((t + 1) * BK); fetchB((t + 1) * BK); }

        load_frag(0, 0);
        #pragma unroll
        for (int k = 0; k < BK; k++) {
            const int s = k & 1;
            if (k + 1 < BK) load_frag(k + 1, s ^ 1);
            if (k == 9  && hn) storeA(cur ^ 1);
            if (k == 13 && hn) storeB(cur ^ 1);
            #pragma unroll
            for (int i = 0; i < 8; i++)
                #pragma unroll
                for (int j = 0; j < 8; j++)
                    acc[i][j] = fmaf(a_fr[s][i], b_fr[s][j], acc[i][j]);
        }
        __syncthreads();
        if (hn) cur ^= 1;
    }

    // Epilogue: bias after full K sum (reference order).
    float4 bb0 = *reinterpret_cast<const float4*>(bias + n0 + tx * 4);
    float4 bb1 = *reinterpret_cast<const float4*>(bias + n0 + 64 + tx * 4);

    #pragma unroll
    for (int i = 0; i < 8; i++) {
        int m = m0 + ((i < 4) ? (ty * 4 + i) : (64 + ty * 4 + (i - 4)));
        size_t off = (size_t)m * N + n0;
        float4 v0 = make_float4(__fadd_rn(acc[i][0], bb0.x),
                                __fadd_rn(acc[i][1], bb0.y),
                                __fadd_rn(acc[i][2], bb0.z),
                                __fadd_rn(acc[i][3], bb0.w));
        float4 v1 = make_float4(__fadd_rn(acc[i][4], bb1.x),
                                __fadd_rn(acc[i][5], bb1.y),
                                __fadd_rn(acc[i][6], bb1.z),
                                __fadd_rn(acc[i][7], bb1.w));
        *reinterpret_cast<float4*>(C + off + tx * 4)      = v0;
        *reinterpret_cast<float4*>(C + off + 64 + tx * 4) = v1;
    }
}

// ============ small GEMM (prologue h1 only) ================================
#define SBM 128
#define SBN 64
#define SBK 16

template<int ACT>
__global__ void __launch_bounds__(256, 4) gemm_kernel(
    const float* __restrict__ A, int lda,
    const float* __restrict__ W, int ldw,
    const float* __restrict__ bias,
    float* __restrict__ C,
    int N, int K)
{
    __shared__ float As[SBK][SBM + 4];
    __shared__ float Bs[SBK][SBN + 4];

    const int tid = threadIdx.x;
    const int tx  = tid & 15;
    const int ty  = tid >> 4;
    const int m0  = blockIdx.y * SBM;
    const int n0  = blockIdx.x * SBN;

    float acc[8][4];
    #pragma unroll
    for (int i = 0; i < 8; i++)
        #pragma unroll
        for (int j = 0; j < 4; j++) acc[i][j] = 0.f;

    for (int kt = 0; kt < K; kt += SBK) {
        #pragma unroll
        for (int l = 0; l < 2; l++) {
            int idx4 = tid + l * 256;
            int r = idx4 >> 2, c4 = idx4 & 3;
            float4 v = *reinterpret_cast<const float4*>(
                A + (size_t)(m0 + r) * lda + kt + c4 * 4);
            As[c4*4+0][r] = v.x; As[c4*4+1][r] = v.y;
            As[c4*4+2][r] = v.z; As[c4*4+3][r] = v.w;
        }
        {
            int r = tid >> 2, c4 = tid & 3;
            float4 v = *reinterpret_cast<const float4*>(
                W + (size_t)(n0 + r) * ldw + kt + c4 * 4);
            Bs[c4*4+0][r] = v.x; Bs[c4*4+1][r] = v.y;
            Bs[c4*4+2][r] = v.z; Bs[c4*4+3][r] = v.w;
        }
        __syncthreads();

        #pragma unroll
        for (int k = 0; k < SBK; k++) {
            float4 a0 = *reinterpret_cast<const float4*>(&As[k][ty * 8]);
            float4 a1 = *reinterpret_cast<const float4*>(&As[k][ty * 8 + 4]);
            float4 b0 = *reinterpret_cast<const float4*>(&Bs[k][tx * 4]);
            float av[8] = {a0.x, a0.y, a0.z, a0.w, a1.x, a1.y, a1.z, a1.w};
            float bv[4] = {b0.x, b0.y, b0.z, b0.w};
            #pragma unroll
            for (int i = 0; i < 8; i++)
                #pragma unroll
                for (int j = 0; j < 4; j++)
                    acc[i][j] = fmaf(av[i], bv[j], acc[i][j]);
        }
        __syncthreads();
    }

    float4 b4 = make_float4(0.f, 0.f, 0.f, 0.f);
    if (bias) b4 = *reinterpret_cast<const float4*>(bias + n0 + tx * 4);

    #pragma unroll
    for (int i = 0; i < 8; i++) {
        int m = m0 + ty * 8 + i;
        size_t off = (size_t)m * N + n0 + tx * 4;
        float4 v = make_float4(__fadd_rn(acc[i][0], b4.x),
                               __fadd_rn(acc[i][1], b4.y),
                               __fadd_rn(acc[i][2], b4.z),
                               __fadd_rn(acc[i][3], b4.w));
        if (ACT == 1) {
            v.x = tanhf(v.x); v.y = tanhf(v.y);
            v.z = tanhf(v.z); v.w = tanhf(v.w);
        }
        *reinterpret_cast<float4*>(C + off) = v;
    }
}

// ============ W_out GEMM: 32x64 tiles, 256 blocks (fills the chip) =========
// C[B,D] = A[B,H] @ W[D,H]^T + bias. Serial ascending-k chain preserved.
#define WBM 32
#define WBN 64
#define WBK 16

__global__ void __launch_bounds__(256, 4) gemm_wout_kernel(
    const float* __restrict__ A,
    const float* __restrict__ W,
    const float* __restrict__ bias,
    float* __restrict__ C)
{
    __shared__ float As[WBK][WBM + 4];
    __shared__ float Bs[WBK][WBN + 4];

    const int tid = threadIdx.x;
    const int tx  = tid & 15;     // 16 x 4 = 64 n
    const int ty  = tid >> 4;     // 16 x 2 = 32 m
    const int m0  = blockIdx.y * WBM;
    const int n0  = blockIdx.x * WBN;

    float acc[2][4];
    #pragma unroll
    for (int i = 0; i < 2; i++)
        #pragma unroll
        for (int j = 0; j < 4; j++) acc[i][j] = 0.f;

    for (int kt = 0; kt < H; kt += WBK) {
        if (tid < 128) {                       // A tile: 32x16 = 128 float4
            int r = tid >> 2, c4 = tid & 3;
            float4 v = *reinterpret_cast<const float4*>(
                A + (size_t)(m0 + r) * H + kt + c4 * 4);
            As[c4*4+0][r] = v.x; As[c4*4+1][r] = v.y;
            As[c4*4+2][r] = v.z; As[c4*4+3][r] = v.w;
        }
        {                                      // B tile: 64x16 = 256 float4
            int r = tid >> 2, c4 = tid & 3;
            float4 v = *reinterpret_cast<const float4*>(
                W + (size_t)(n0 + r) * H + kt + c4 * 4);
            Bs[c4*4+0][r] = v.x; Bs[c4*4+1][r] = v.y;
            Bs[c4*4+2][r] = v.z; Bs[c4*4+3][r] = v.w;
        }
        __syncthreads();

        #pragma unroll
        for (int k = 0; k < WBK; k++) {
            float a0 = As[k][ty * 2];
            float a1 = As[k][ty * 2 + 1];
            float4 b = *reinterpret_cast<const float4*>(&Bs[k][tx * 4]);
            float bv[4] = {b.x, b.y, b.z, b.w};
            #pragma unroll
            for (int j = 0; j < 4; j++) {
                acc[0][j] = fmaf(a0, bv[j], acc[0][j]);
                acc[1][j] = fmaf(a1, bv[j], acc[1][j]);
            }
        }
        __syncthreads();
    }

    float4 b4 = *reinterpret_cast<const float4*>(bias + n0 + tx * 4);
    #pragma unroll
    for (int i = 0; i < 2; i++) {
        int m = m0 + ty * 2 + i;
        size_t off = (size_t)m * D + n0 + tx * 4;
        float4 v = make_float4(__fadd_rn(acc[i][0], b4.x),
                               __fadd_rn(acc[i][1], b4.y),
                               __fadd_rn(acc[i][2], b4.z),
                               __fadd_rn(acc[i][3], b4.w));
        *reinterpret_cast<float4*>(C + off) = v;
    }
}

// ---------------- GRU gate fusion (float4-vectorized, unchanged) -----------
__global__ void gru_gate_kernel(const float* __restrict__ gi,
                                const float* __restrict__ gh,
                                float* __restrict__ h,
                                float* __restrict__ copy_dst)
{
    int q = blockIdx.x * blockDim.x + threadIdx.x;   // over B*H/4
    int b = q >> 8;
    int j4 = (q & 255) << 2;
    size_t base = (size_t)b * G3H + j4;
    size_t hoff = (size_t)b * H + j4;

    float4 ir4 = *reinterpret_cast<const float4*>(gi + base);
    float4 iz4 = *reinterpret_cast<const float4*>(gi + base + H);
    float4 in4 = *reinterpret_cast<const float4*>(gi + base + 2 * H);
    float4 hr4 = *reinterpret_cast<const float4*>(gh + base);
    float4 hz4 = *reinterpret_cast<const float4*>(gh + base + H);
    float4 hn4 = *reinterpret_cast<const float4*>(gh + base + 2 * H);
    float4 h4  = *reinterpret_cast<const float4*>(h + hoff);

    float hv[4];
    const float ir[4] = {ir4.x, ir4.y, ir4.z, ir4.w};
    const float iz[4] = {iz4.x, iz4.y, iz4.z, iz4.w};
    const float in_[4] = {in4.x, in4.y, in4.z, in4.w};
    const float hr[4] = {hr4.x, hr4.y, hr4.z, hr4.w};
    const float hz[4] = {hz4.x, hz4.y, hz4.z, hz4.w};
    const float hn[4] = {hn4.x, hn4.y, hn4.z, hn4.w};
    const float hp[4] = {h4.x, h4.y, h4.z, h4.w};

    #pragma unroll
    for (int e = 0; e < 4; e++) {
        float sr = __fadd_rn(ir[e], hr[e]);
        float sz = __fadd_rn(iz[e], hz[e]);
        float r  = __fdiv_rn(1.f, __fadd_rn(1.f, expf(-sr)));
        float zg = __fdiv_rn(1.f, __fadd_rn(1.f, expf(-sz)));
        float n  = tanhf(__fadd_rn(in_[e], __fmul_rn(r, hn[e])));
        hv[e] = __fadd_rn(__fmul_rn(__fsub_rn(1.f, zg), n),
                          __fmul_rn(zg, hp[e]));
    }
    float4 hv4 = make_float4(hv[0], hv[1], hv[2], hv[3]);
    *reinterpret_cast<float4*>(h + hoff) = hv4;
    if (copy_dst) *reinterpret_cast<float4*>(copy_dst + hoff) = hv4;
}

// ---------------- paired log-softmax + argmax + one-hot (unchanged) --------
__global__ void softmax_kernel(const float* __restrict__ tmp,
                               float* __restrict__ inp,
                               float* __restrict__ dout, int t)
{
    int i = blockIdx.x * blockDim.x + threadIdx.x;
    int b = i >> 7;
    int f = i & 127;
    float a = tmp[(size_t)b * D + f];
    float c = tmp[(size_t)b * D + 128 + f];
    float m  = fmaxf(a, c);
    float sa = __fsub_rn(a, m);
    float sc = __fsub_rn(c, m);
    float lse = logf(__fadd_rn(expf(sa), expf(sc)));
    float la = __fsub_rn(sa, lse);
    float lc = __fsub_rn(sc, lse);
    size_t ob = (size_t)b * NSTEP * D + (size_t)t * D;
    dout[ob + f]       = la;
    dout[ob + 128 + f] = lc;
    int idx = (la >= lc) ? 0 : 1;
    inp[(size_t)b * KIN + 2 * f]     = (idx == 0) ? 1.f : 0.f;
    inp[(size_t)b * KIN + 2 * f + 1] = (idx == 1) ? 1.f : 0.f;
}

__global__ void init_inp_kernel(const float* __restrict__ z,
                                float* __restrict__ inp)
{
    int i = blockIdx.x * blockDim.x + threadIdx.x;
    int b = i >> 9;
    int j = i & (KIN - 1);
    float v;
    if (j < D) v = (j == D - 1) ? 1.f : 0.f;
    else       v = z[(size_t)b * L + (j - D)];
    inp[i] = v;
}

// ---------------- launch ---------------------------------------------------
extern "C" void kernel_launch(void* const* d_in, const int* in_sizes, int n_in,
                              void* d_out, int out_size)
{
    (void)in_sizes; (void)n_in; (void)out_size;
    const float* z      = (const float*)d_in[0];
    const float* W_init = (const float*)d_in[1];
    const float* b_init = (const float*)d_in[2];
    const float* W_ih1  = (const float*)d_in[3];   // [3072, 512]
    const float* W_hh1  = (const float*)d_in[4];   // [3072, 1024]
    const float* b_ih1  = (const float*)d_in[5];
    const float* b_hh1  = (const float*)d_in[6];
    const float* W_ih2  = (const float*)d_in[7];
    const float* W_hh2  = (const float*)d_in[8];
    const float* b_ih2  = (const float*)d_in[9];
    const float* b_hh2  = (const float*)d_in[10];
    const float* W_out  = (const float*)d_in[11];  // [256, 1024]
    const float* b_out  = (const float*)d_in[12];
    float* out = (float*)d_out;

    float *inp, *gi, *gh, *h1, *h2, *tb;
    cudaGetSymbolAddress((void**)&inp, g_inp);
    cudaGetSymbolAddress((void**)&gi,  g_gi);
    cudaGetSymbolAddress((void**)&gh,  g_gh);
    cudaGetSymbolAddress((void**)&h1,  g_h1);
    cudaGetSymbolAddress((void**)&h2,  g_h2);
    cudaGetSymbolAddress((void**)&tb,  g_tmp);

    const dim3 blk(256);
    const dim3 grid_pair(G3H / BN, B / BM, 2);    // 24 x 16 x 2
    const dim3 grid_h   (H / SBN, B / SBM);
    const dim3 grid_wout(D / WBN, B / WBM);       // 4 x 64 = 256 blocks

    // launch 0: dummy (aligns ncu -s 5 onto pair2 = gemm_big)
    dummy_kernel<<<1, 32>>>();
    // Prologue
    init_inp_kernel<<<(B * KIN) / 256, blk>>>(z, inp);
    gemm_kernel<1><<<grid_h, blk>>>(z, L, W_init, L, b_init, h1, H, L);

    for (int t = 0; t < NSTEP; t++) {
        // layer 1: HEAVY gh1 (K=1024) at z=0, light gi1 (K=512) fills tail
        gemm_big_kernel<<<grid_pair, blk>>>(
            h1,  H,   W_hh1, H,   b_hh1, gh, H,
            inp, KIN, W_ih1, KIN, b_ih1, gi, KIN,
            G3H);
        gru_gate_kernel<<<(B * H / 4) / 256, blk>>>(gi, gh, h1,
                                                    (t == 0) ? h2 : nullptr);
        // layer 2: gi2 + gh2 (both K=1024)
        gemm_big_kernel<<<grid_pair, blk>>>(
            h1, H, W_ih2, H, b_ih2, gi, H,
            h2, H, W_hh2, H, b_hh2, gh, H,
            G3H);
        gru_gate_kernel<<<(B * H / 4) / 256, blk>>>(gi, gh, h2, nullptr);
        // logits (256-block tiling)
        gemm_wout_kernel<<<grid_wout, blk>>>(h2, W_out, b_out, tb);
        softmax_kernel<<<(B * 128) / 256, blk>>>(tb, inp, out, t);
    }
}